// round 5
// baseline (speedup 1.0000x reference)
#include <cuda_runtime.h>
#include <cuda_fp16.h>
#include <cstdint>

#define B_   384
#define IN_  512
#define OUT_ 384

// ---------------- device-global scratch ----------------
__device__ __half g_T16[(size_t)B_ * IN_ * OUT_];  // T[b][i][p]  (rows (b,i), cols p)
__device__ __half g_Wf[OUT_ * IN_];                // fp16(W)   [o][i]
__device__ __half g_WfT[IN_ * OUT_];               // fp16(W)^T [i][o]
__device__ float  g_sp[OUT_ * IN_];
__device__ float  g_dp[B_ * IN_];
__device__ float  g_s1s3[B_ * OUT_];

// ---------------- prep ----------------
__global__ void prep_kernel(const float* __restrict__ sw,
                            const float* __restrict__ mu,
                            const float* __restrict__ sigma,
                            const float* __restrict__ W,
                            float* __restrict__ sp, float* __restrict__ dp,
                            __half* __restrict__ Wf, __half* __restrict__ WfT) {
    int idx = blockIdx.x * blockDim.x + threadIdx.x;
    if (idx >= OUT_ * IN_) return;
    sp[idx] = log1pf(expf(sw[idx]));
    float w = W[idx];
    __half wh = __float2half(w);
    Wf[idx] = wh;
    int o = idx >> 9, i = idx & 511;
    WfT[i * OUT_ + o] = wh;
    int b = o;  // B_*IN_ == OUT_*IN_
    float m = mu[idx];
    dp[idx] = sigma[(size_t)b * (IN_ * IN_) + (size_t)i * (IN_ + 1)] + m * m;
}

// ---------------- small fp32 GEMM (mu_f, s1s3) ----------------
#define BMF 128
#define BNF 128
#define BKF 16
__device__ __forceinline__ unsigned long long pack2(float lo, float hi) {
    unsigned long long d; asm("mov.b64 %0, {%1, %2};" : "=l"(d) : "f"(lo), "f"(hi)); return d;
}
__device__ __forceinline__ unsigned long long dup2(float v) {
    unsigned long long d; asm("mov.b64 %0, {%1, %1};" : "=l"(d) : "f"(v)); return d;
}
__device__ __forceinline__ void unpack2(unsigned long long d, float& lo, float& hi) {
    asm("mov.b64 {%0, %1}, %2;" : "=f"(lo), "=f"(hi) : "l"(d));
}
__device__ __forceinline__ void fma2(unsigned long long& a, unsigned long long x,
                                     unsigned long long y) {
    asm("fma.rn.f32x2 %0, %1, %2, %0;" : "+l"(a) : "l"(x), "l"(y));
}
template <int EPI>
__global__ __launch_bounds__(256)
void gemm_f32(const float* __restrict__ A, const float* __restrict__ Bm,
              float* __restrict__ C, const float* __restrict__ aux,
              int M, int N, int K) {
    __shared__ float As[BKF][BMF + 4];
    __shared__ float Bs[BKF][BNF + 4];
    const int bm = blockIdx.y * BMF, bn = blockIdx.x * BNF;
    const int tid = threadIdx.x, tx = tid & 15, ty = tid >> 4;
    unsigned long long acc[8][4];
#pragma unroll
    for (int i = 0; i < 8; i++)
#pragma unroll
        for (int j = 0; j < 4; j++) acc[i][j] = 0ull;
    const int lr = tid >> 2, lq = tid & 3;
    for (int k0 = 0; k0 < K; k0 += BKF) {
#pragma unroll
        for (int l = 0; l < 2; l++) {
            int row = lr + l * 64;
            float4 v = *(const float4*)(A + (long)(bm + row) * K + k0 + lq * 4);
            As[lq * 4 + 0][row] = v.x; As[lq * 4 + 1][row] = v.y;
            As[lq * 4 + 2][row] = v.z; As[lq * 4 + 3][row] = v.w;
            float4 w = *(const float4*)(Bm + (long)(bn + row) * K + k0 + lq * 4);
            Bs[lq * 4 + 0][row] = w.x; Bs[lq * 4 + 1][row] = w.y;
            Bs[lq * 4 + 2][row] = w.z; Bs[lq * 4 + 3][row] = w.w;
        }
        __syncthreads();
#pragma unroll
        for (int k = 0; k < BKF; k++) {
            float4 a0 = *(const float4*)&As[k][ty * 8];
            float4 a1 = *(const float4*)&As[k][ty * 8 + 4];
            float4 b0 = *(const float4*)&Bs[k][tx * 8];
            float4 b1 = *(const float4*)&Bs[k][tx * 8 + 4];
            unsigned long long bb[4] = {pack2(b0.x, b0.y), pack2(b0.z, b0.w),
                                        pack2(b1.x, b1.y), pack2(b1.z, b1.w)};
            float av[8] = {a0.x, a0.y, a0.z, a0.w, a1.x, a1.y, a1.z, a1.w};
#pragma unroll
            for (int i = 0; i < 8; i++) {
                unsigned long long ad = dup2(av[i]);
#pragma unroll
                for (int j = 0; j < 4; j++) fma2(acc[i][j], ad, bb[j]);
            }
        }
        __syncthreads();
    }
#pragma unroll
    for (int i = 0; i < 8; i++) {
        int gm = bm + ty * 8 + i;
        float o[8];
#pragma unroll
        for (int j = 0; j < 4; j++) unpack2(acc[i][j], o[2 * j], o[2 * j + 1]);
#pragma unroll
        for (int j = 0; j < 8; j++) {
            int gn = bn + tx * 8 + j;
            if (EPI == 1) o[j] += aux[gn];
            if (EPI == 2) { if (gm == gn) o[j] += aux[gn]; }
        }
        float* cp = C + (long)gm * N + bn + tx * 8;
        *(float4*)(cp) = make_float4(o[0], o[1], o[2], o[3]);
        *(float4*)(cp + 4) = make_float4(o[4], o[5], o[6], o[7]);
    }
}

// ---------------- HMMA helpers ----------------
__device__ __forceinline__ uint32_t smem_u32(const void* p) {
    uint32_t a;
    asm("{ .reg .u64 t; cvta.to.shared.u64 t, %1; cvt.u32.u64 %0, t; }" : "=r"(a) : "l"(p));
    return a;
}
__device__ __forceinline__ void ldsm_x4(uint32_t* r, uint32_t addr) {
    asm volatile("ldmatrix.sync.aligned.m8n8.x4.shared.b16 {%0,%1,%2,%3}, [%4];"
                 : "=r"(r[0]), "=r"(r[1]), "=r"(r[2]), "=r"(r[3]) : "r"(addr));
}
__device__ __forceinline__ void ldsm_x4_t(uint32_t* r, uint32_t addr) {
    asm volatile("ldmatrix.sync.aligned.m8n8.x4.trans.shared.b16 {%0,%1,%2,%3}, [%4];"
                 : "=r"(r[0]), "=r"(r[1]), "=r"(r[2]), "=r"(r[3]) : "r"(addr));
}
__device__ __forceinline__ void mma16816(float* c, const uint32_t* a, const uint32_t* b) {
    asm volatile(
        "mma.sync.aligned.m16n8k16.row.col.f32.f16.f16.f32 "
        "{%0,%1,%2,%3}, {%4,%5,%6,%7}, {%8,%9}, {%0,%1,%2,%3};"
        : "+f"(c[0]), "+f"(c[1]), "+f"(c[2]), "+f"(c[3])
        : "r"(a[0]), "r"(a[1]), "r"(a[2]), "r"(a[3]), "r"(b[0]), "r"(b[1]));
}

// ---------------- main HMMA GEMM ----------------
// D[m, n] = sum_k A[m,k] * Bk[k,n]
// STAGE 1: A = sigma (fp32->fp16), Bk = WfT, D -> T (fp16, row-major)
// STAGE 2: A = Wf rows (o-block),  Bk = T[b],  D -> out rows (b,o) + diag
#define BM 128
#define BN 128
#define BK 32
#define LDA 40   // As row stride (halves)
#define LDB 136  // Bs row stride (halves)

template <int STAGE>
__global__ __launch_bounds__(256)
void hgemm(const float* __restrict__ A32, const __half* __restrict__ A16,
           const __half* __restrict__ Bsrc0, void* __restrict__ Dout,
           const float* __restrict__ s1s3) {
    __shared__ __half As[2][BM][LDA];
    __shared__ __half Bs[2][BK][LDB];

    const int tid = threadIdx.x, lane = tid & 31, wid = tid >> 5;
    const int wm = wid & 1, wn = wid >> 1;
    const int mb = blockIdx.y, nb = blockIdx.x;
    const size_t m0 = (size_t)mb * BM;
    const int n0 = nb * BN;

    // per-stage source pointers
    const int b_idx = (STAGE == 2) ? (mb / 3) : 0;
    const int o0    = (STAGE == 2) ? ((mb % 3) * BM) : 0;
    const __half* Bsrc = (STAGE == 2)
        ? Bsrc0 + (size_t)b_idx * IN_ * OUT_   // T[b]: [i][p]
        : Bsrc0;                               // WfT:  [i][o]

    // fill mappings
    const int ar = tid >> 1, akc = (tid & 1) * 16;        // A: row, 16-col chunk
    const int bkr = tid >> 3, bnc = (tid & 7) * 16;       // B: k-row, 16-col chunk

    float c[4][4][4];
#pragma unroll
    for (int i = 0; i < 4; i++)
#pragma unroll
        for (int j = 0; j < 4; j++)
#pragma unroll
            for (int l = 0; l < 4; l++) c[i][j][l] = 0.f;

    // staging registers
    float  fa[16];
    uint4  ha[2];
    uint4  hb[2];

    auto load_regs = [&](int kt) {
        const int k0 = kt * BK;
        if (STAGE == 1) {
            const float* s = A32 + (m0 + ar) * IN_ + k0 + akc;
#pragma unroll
            for (int q = 0; q < 4; q++) {
                float4 v = *(const float4*)(s + q * 4);
                fa[q * 4 + 0] = v.x; fa[q * 4 + 1] = v.y;
                fa[q * 4 + 2] = v.z; fa[q * 4 + 3] = v.w;
            }
        } else {
            const __half* s = A16 + (size_t)(o0 + ar) * IN_ + k0 + akc;
            ha[0] = *(const uint4*)(s);
            ha[1] = *(const uint4*)(s + 8);
        }
        const __half* bs = Bsrc + (size_t)(k0 + bkr) * OUT_ + n0 + bnc;
        hb[0] = *(const uint4*)(bs);
        hb[1] = *(const uint4*)(bs + 8);
    };
    auto sts = [&](int buf) {
        if (STAGE == 1) {
            __half h[16];
#pragma unroll
            for (int q = 0; q < 16; q++) h[q] = __float2half(fa[q]);
            *(uint4*)&As[buf][ar][akc]     = *(uint4*)&h[0];
            *(uint4*)&As[buf][ar][akc + 8] = *(uint4*)&h[8];
        } else {
            *(uint4*)&As[buf][ar][akc]     = ha[0];
            *(uint4*)&As[buf][ar][akc + 8] = ha[1];
        }
        *(uint4*)&Bs[buf][bkr][bnc]     = hb[0];
        *(uint4*)&Bs[buf][bkr][bnc + 8] = hb[1];
    };

    const uint32_t as_base = smem_u32(&As[0][0][0]);
    const uint32_t bs_base = smem_u32(&Bs[0][0][0]);
    const int lrow = lane & 15, lcol = (lane >> 4) * 8;

    load_regs(0);
    sts(0);
    __syncthreads();

    const int NKT = IN_ / BK;  // 16
    for (int kt = 0; kt < NKT; kt++) {
        const int cur = kt & 1;
        if (kt + 1 < NKT) load_regs(kt + 1);

#pragma unroll
        for (int ks = 0; ks < 2; ks++) {
            uint32_t af[4][4], bf[4][2];
#pragma unroll
            for (int mt = 0; mt < 4; mt++) {
                uint32_t addr = as_base +
                    ((cur * BM + wm * 64 + mt * 16 + lrow) * LDA + ks * 16 + lcol) * 2;
                ldsm_x4(af[mt], addr);
            }
#pragma unroll
            for (int np = 0; np < 2; np++) {
                uint32_t r[4];
                uint32_t addr = bs_base +
                    ((cur * BK + ks * 16 + lrow) * LDB + wn * 32 + np * 16 + lcol) * 2;
                ldsm_x4_t(r, addr);
                bf[np * 2][0] = r[0]; bf[np * 2][1] = r[1];
                bf[np * 2 + 1][0] = r[2]; bf[np * 2 + 1][1] = r[3];
            }
#pragma unroll
            for (int mt = 0; mt < 4; mt++)
#pragma unroll
                for (int nt = 0; nt < 4; nt++) mma16816(c[mt][nt], af[mt], bf[nt]);
        }
        __syncthreads();
        if (kt + 1 < NKT) {
            sts(cur ^ 1);
            __syncthreads();
        }
    }

    // ---- epilogue
    const int g = lane >> 2, t2 = (lane & 3) * 2;
    const size_t mrow = m0 + wm * 64;
    const int ncol = n0 + wn * 32;

    if (STAGE == 1) {
        __half* T = (__half*)Dout;
#pragma unroll
        for (int mt = 0; mt < 4; mt++)
#pragma unroll
            for (int nt = 0; nt < 4; nt++) {
                size_t r0 = mrow + mt * 16 + g;
                int cc = ncol + nt * 8 + t2;
                *(__half2*)(T + r0 * OUT_ + cc) =
                    __floats2half2_rn(c[mt][nt][0], c[mt][nt][1]);
                *(__half2*)(T + (r0 + 8) * OUT_ + cc) =
                    __floats2half2_rn(c[mt][nt][2], c[mt][nt][3]);
            }
    } else {
        float* O = (float*)Dout;
#pragma unroll
        for (int mt = 0; mt < 4; mt++)
#pragma unroll
            for (int nt = 0; nt < 4; nt++) {
                int cc = ncol + nt * 8 + t2;
#pragma unroll
                for (int h = 0; h < 2; h++) {
                    size_t m = mrow + mt * 16 + g + h * 8;
                    int o = (int)(m - (size_t)b_idx * OUT_);
                    float v0 = c[mt][nt][h * 2], v1 = c[mt][nt][h * 2 + 1];
                    if (cc == o)     v0 += s1s3[m];
                    if (cc + 1 == o) v1 += s1s3[m];
                    float2* p = (float2*)(O + m * OUT_ + cc);
                    *p = make_float2(v0, v1);
                }
            }
    }
}

// ---------------- launch ----------------
extern "C" void kernel_launch(void* const* d_in, const int* in_sizes, int n_in,
                              void* d_out, int out_size) {
    const float* mu    = (const float*)d_in[0];
    const float* sigma = (const float*)d_in[1];
    const float* W     = (const float*)d_in[2];
    const float* bias  = (const float*)d_in[3];
    const float* sw    = (const float*)d_in[4];
    const float* sbias = (const float*)d_in[5];
    float* out = (float*)d_out;

    float *sp, *dp, *s1s3;
    __half *T16, *Wf, *WfT;
    cudaGetSymbolAddress((void**)&sp,   g_sp);
    cudaGetSymbolAddress((void**)&dp,   g_dp);
    cudaGetSymbolAddress((void**)&s1s3, g_s1s3);
    cudaGetSymbolAddress((void**)&T16,  g_T16);
    cudaGetSymbolAddress((void**)&Wf,   g_Wf);
    cudaGetSymbolAddress((void**)&WfT,  g_WfT);

    prep_kernel<<<(OUT_ * IN_ + 255) / 256, 256>>>(sw, mu, sigma, W, sp, dp, Wf, WfT);

    // mu_f and s1s3 (fp32, exact)
    gemm_f32<1><<<dim3(OUT_ / BNF, B_ / BMF), 256>>>(mu, W, out, bias, B_, OUT_, IN_);
    gemm_f32<2><<<dim3(OUT_ / BNF, B_ / BMF), 256>>>(dp, sp, s1s3, sbias, B_, OUT_, IN_);

    // stage 1: T[(b,i), p] = sum_j sigma[b,i,j] * W[p,j]   (M = 196608)
    hgemm<1><<<dim3(OUT_ / BN, (B_ * IN_) / BM), 256>>>(
        sigma, nullptr, WfT, T16, nullptr);

    // stage 2: out[(b,o), p] = sum_i W[o,i] * T[b,i,p] + diag  (M = 147456)
    hgemm<2><<<dim3(OUT_ / BN, (B_ * OUT_) / BM), 256>>>(
        nullptr, Wf, T16, out + (size_t)B_ * OUT_, s1s3);
}

// round 6
// speedup vs baseline: 1.0010x; 1.0010x over previous
#include <cuda_runtime.h>
#include <cuda_fp16.h>
#include <cstdint>

#define B_   384
#define IN_  512
#define OUT_ 384

// ---------------- device-global scratch ----------------
__device__ __half g_T16[(size_t)B_ * IN_ * OUT_];  // T[b][i][p]  (rows (b,i), cols p)
__device__ __half g_Wf[OUT_ * IN_];                // fp16(W)   [o][i]
__device__ __half g_WfT[IN_ * OUT_];               // fp16(W)^T [i][o]
__device__ float  g_sp[OUT_ * IN_];
__device__ float  g_dp[B_ * IN_];
__device__ float  g_s1s3[B_ * OUT_];

// ---------------- prep ----------------
__global__ void prep_kernel(const float* __restrict__ sw,
                            const float* __restrict__ mu,
                            const float* __restrict__ sigma,
                            const float* __restrict__ W,
                            float* __restrict__ sp, float* __restrict__ dp,
                            __half* __restrict__ Wf, __half* __restrict__ WfT) {
    int idx = blockIdx.x * blockDim.x + threadIdx.x;
    if (idx >= OUT_ * IN_) return;
    sp[idx] = log1pf(expf(sw[idx]));
    float w = W[idx];
    __half wh = __float2half(w);
    Wf[idx] = wh;
    int o = idx >> 9, i = idx & 511;
    WfT[i * OUT_ + o] = wh;
    int b = o;  // B_*IN_ == OUT_*IN_
    float m = mu[idx];
    dp[idx] = sigma[(size_t)b * (IN_ * IN_) + (size_t)i * (IN_ + 1)] + m * m;
}

// ---------------- small fp32 GEMM (mu_f, s1s3) ----------------
#define BMF 128
#define BNF 128
#define BKF 16
__device__ __forceinline__ unsigned long long pack2(float lo, float hi) {
    unsigned long long d; asm("mov.b64 %0, {%1, %2};" : "=l"(d) : "f"(lo), "f"(hi)); return d;
}
__device__ __forceinline__ unsigned long long dup2(float v) {
    unsigned long long d; asm("mov.b64 %0, {%1, %1};" : "=l"(d) : "f"(v)); return d;
}
__device__ __forceinline__ void unpack2(unsigned long long d, float& lo, float& hi) {
    asm("mov.b64 {%0, %1}, %2;" : "=f"(lo), "=f"(hi) : "l"(d));
}
__device__ __forceinline__ void fma2(unsigned long long& a, unsigned long long x,
                                     unsigned long long y) {
    asm("fma.rn.f32x2 %0, %1, %2, %0;" : "+l"(a) : "l"(x), "l"(y));
}
template <int EPI>
__global__ __launch_bounds__(256)
void gemm_f32(const float* __restrict__ A, const float* __restrict__ Bm,
              float* __restrict__ C, const float* __restrict__ aux,
              int M, int N, int K) {
    __shared__ float As[BKF][BMF + 4];
    __shared__ float Bs[BKF][BNF + 4];
    const int bm = blockIdx.y * BMF, bn = blockIdx.x * BNF;
    const int tid = threadIdx.x, tx = tid & 15, ty = tid >> 4;
    unsigned long long acc[8][4];
#pragma unroll
    for (int i = 0; i < 8; i++)
#pragma unroll
        for (int j = 0; j < 4; j++) acc[i][j] = 0ull;
    const int lr = tid >> 2, lq = tid & 3;
    for (int k0 = 0; k0 < K; k0 += BKF) {
#pragma unroll
        for (int l = 0; l < 2; l++) {
            int row = lr + l * 64;
            float4 v = *(const float4*)(A + (long)(bm + row) * K + k0 + lq * 4);
            As[lq * 4 + 0][row] = v.x; As[lq * 4 + 1][row] = v.y;
            As[lq * 4 + 2][row] = v.z; As[lq * 4 + 3][row] = v.w;
            float4 w = *(const float4*)(Bm + (long)(bn + row) * K + k0 + lq * 4);
            Bs[lq * 4 + 0][row] = w.x; Bs[lq * 4 + 1][row] = w.y;
            Bs[lq * 4 + 2][row] = w.z; Bs[lq * 4 + 3][row] = w.w;
        }
        __syncthreads();
#pragma unroll
        for (int k = 0; k < BKF; k++) {
            float4 a0 = *(const float4*)&As[k][ty * 8];
            float4 a1 = *(const float4*)&As[k][ty * 8 + 4];
            float4 b0 = *(const float4*)&Bs[k][tx * 8];
            float4 b1 = *(const float4*)&Bs[k][tx * 8 + 4];
            unsigned long long bb[4] = {pack2(b0.x, b0.y), pack2(b0.z, b0.w),
                                        pack2(b1.x, b1.y), pack2(b1.z, b1.w)};
            float av[8] = {a0.x, a0.y, a0.z, a0.w, a1.x, a1.y, a1.z, a1.w};
#pragma unroll
            for (int i = 0; i < 8; i++) {
                unsigned long long ad = dup2(av[i]);
#pragma unroll
                for (int j = 0; j < 4; j++) fma2(acc[i][j], ad, bb[j]);
            }
        }
        __syncthreads();
    }
#pragma unroll
    for (int i = 0; i < 8; i++) {
        int gm = bm + ty * 8 + i;
        float o[8];
#pragma unroll
        for (int j = 0; j < 4; j++) unpack2(acc[i][j], o[2 * j], o[2 * j + 1]);
#pragma unroll
        for (int j = 0; j < 8; j++) {
            int gn = bn + tx * 8 + j;
            if (EPI == 1) o[j] += aux[gn];
            if (EPI == 2) { if (gm == gn) o[j] += aux[gn]; }
        }
        float* cp = C + (long)gm * N + bn + tx * 8;
        *(float4*)(cp) = make_float4(o[0], o[1], o[2], o[3]);
        *(float4*)(cp + 4) = make_float4(o[4], o[5], o[6], o[7]);
    }
}

// ---------------- HMMA helpers ----------------
__device__ __forceinline__ uint32_t smem_u32(const void* p) {
    uint32_t a;
    asm("{ .reg .u64 t; cvta.to.shared.u64 t, %1; cvt.u32.u64 %0, t; }" : "=r"(a) : "l"(p));
    return a;
}
__device__ __forceinline__ void ldsm_x4(uint32_t* r, uint32_t addr) {
    asm volatile("ldmatrix.sync.aligned.m8n8.x4.shared.b16 {%0,%1,%2,%3}, [%4];"
                 : "=r"(r[0]), "=r"(r[1]), "=r"(r[2]), "=r"(r[3]) : "r"(addr));
}
__device__ __forceinline__ void ldsm_x4_t(uint32_t* r, uint32_t addr) {
    asm volatile("ldmatrix.sync.aligned.m8n8.x4.trans.shared.b16 {%0,%1,%2,%3}, [%4];"
                 : "=r"(r[0]), "=r"(r[1]), "=r"(r[2]), "=r"(r[3]) : "r"(addr));
}
__device__ __forceinline__ void mma16816(float* c, const uint32_t* a, const uint32_t* b) {
    asm volatile(
        "mma.sync.aligned.m16n8k16.row.col.f32.f16.f16.f32 "
        "{%0,%1,%2,%3}, {%4,%5,%6,%7}, {%8,%9}, {%0,%1,%2,%3};"
        : "+f"(c[0]), "+f"(c[1]), "+f"(c[2]), "+f"(c[3])
        : "r"(a[0]), "r"(a[1]), "r"(a[2]), "r"(a[3]), "r"(b[0]), "r"(b[1]));
}

// ---------------- main HMMA GEMM ----------------
// D[m, n] = sum_k A[m,k] * Bk[k,n]
// STAGE 1: A = sigma (fp32->fp16), Bk = WfT, D -> T (fp16, row-major)
// STAGE 2: A = Wf rows (o-block),  Bk = T[b],  D -> out rows (b,o) + diag
#define BM 128
#define BN 128
#define BK 32
#define LDA 40   // As row stride (halves)
#define LDB 136  // Bs row stride (halves)

template <int STAGE>
__global__ __launch_bounds__(256)
void hgemm(const float* __restrict__ A32, const __half* __restrict__ A16,
           const __half* __restrict__ Bsrc0, void* __restrict__ Dout,
           const float* __restrict__ s1s3) {
    __shared__ __half As[2][BM][LDA];
    __shared__ __half Bs[2][BK][LDB];

    const int tid = threadIdx.x, lane = tid & 31, wid = tid >> 5;
    const int wm = wid & 1, wn = wid >> 1;
    const int mb = blockIdx.y, nb = blockIdx.x;
    const size_t m0 = (size_t)mb * BM;
    const int n0 = nb * BN;

    // per-stage source pointers
    const int b_idx = (STAGE == 2) ? (mb / 3) : 0;
    const int o0    = (STAGE == 2) ? ((mb % 3) * BM) : 0;
    const __half* Bsrc = (STAGE == 2)
        ? Bsrc0 + (size_t)b_idx * IN_ * OUT_   // T[b]: [i][p]
        : Bsrc0;                               // WfT:  [i][o]

    // fill mappings
    const int ar = tid >> 1, akc = (tid & 1) * 16;        // A: row, 16-col chunk
    const int bkr = tid >> 3, bnc = (tid & 7) * 16;       // B: k-row, 16-col chunk

    float c[4][4][4];
#pragma unroll
    for (int i = 0; i < 4; i++)
#pragma unroll
        for (int j = 0; j < 4; j++)
#pragma unroll
            for (int l = 0; l < 4; l++) c[i][j][l] = 0.f;

    // staging registers
    float  fa[16];
    uint4  ha[2];
    uint4  hb[2];

    auto load_regs = [&](int kt) {
        const int k0 = kt * BK;
        if (STAGE == 1) {
            const float* s = A32 + (m0 + ar) * IN_ + k0 + akc;
#pragma unroll
            for (int q = 0; q < 4; q++) {
                float4 v = *(const float4*)(s + q * 4);
                fa[q * 4 + 0] = v.x; fa[q * 4 + 1] = v.y;
                fa[q * 4 + 2] = v.z; fa[q * 4 + 3] = v.w;
            }
        } else {
            const __half* s = A16 + (size_t)(o0 + ar) * IN_ + k0 + akc;
            ha[0] = *(const uint4*)(s);
            ha[1] = *(const uint4*)(s + 8);
        }
        const __half* bs = Bsrc + (size_t)(k0 + bkr) * OUT_ + n0 + bnc;
        hb[0] = *(const uint4*)(bs);
        hb[1] = *(const uint4*)(bs + 8);
    };
    auto sts = [&](int buf) {
        if (STAGE == 1) {
            __half h[16];
#pragma unroll
            for (int q = 0; q < 16; q++) h[q] = __float2half(fa[q]);
            *(uint4*)&As[buf][ar][akc]     = *(uint4*)&h[0];
            *(uint4*)&As[buf][ar][akc + 8] = *(uint4*)&h[8];
        } else {
            *(uint4*)&As[buf][ar][akc]     = ha[0];
            *(uint4*)&As[buf][ar][akc + 8] = ha[1];
        }
        *(uint4*)&Bs[buf][bkr][bnc]     = hb[0];
        *(uint4*)&Bs[buf][bkr][bnc + 8] = hb[1];
    };

    const uint32_t as_base = smem_u32(&As[0][0][0]);
    const uint32_t bs_base = smem_u32(&Bs[0][0][0]);
    const int lrow = lane & 15, lcol = (lane >> 4) * 8;

    load_regs(0);
    sts(0);
    __syncthreads();

    const int NKT = IN_ / BK;  // 16
    for (int kt = 0; kt < NKT; kt++) {
        const int cur = kt & 1;
        if (kt + 1 < NKT) load_regs(kt + 1);

#pragma unroll
        for (int ks = 0; ks < 2; ks++) {
            uint32_t af[4][4], bf[4][2];
#pragma unroll
            for (int mt = 0; mt < 4; mt++) {
                uint32_t addr = as_base +
                    ((cur * BM + wm * 64 + mt * 16 + lrow) * LDA + ks * 16 + lcol) * 2;
                ldsm_x4(af[mt], addr);
            }
#pragma unroll
            for (int np = 0; np < 2; np++) {
                uint32_t r[4];
                uint32_t addr = bs_base +
                    ((cur * BK + ks * 16 + lrow) * LDB + wn * 32 + np * 16 + lcol) * 2;
                ldsm_x4_t(r, addr);
                bf[np * 2][0] = r[0]; bf[np * 2][1] = r[1];
                bf[np * 2 + 1][0] = r[2]; bf[np * 2 + 1][1] = r[3];
            }
#pragma unroll
            for (int mt = 0; mt < 4; mt++)
#pragma unroll
                for (int nt = 0; nt < 4; nt++) mma16816(c[mt][nt], af[mt], bf[nt]);
        }
        __syncthreads();
        if (kt + 1 < NKT) {
            sts(cur ^ 1);
            __syncthreads();
        }
    }

    // ---- epilogue
    const int g = lane >> 2, t2 = (lane & 3) * 2;
    const size_t mrow = m0 + wm * 64;
    const int ncol = n0 + wn * 32;

    if (STAGE == 1) {
        __half* T = (__half*)Dout;
#pragma unroll
        for (int mt = 0; mt < 4; mt++)
#pragma unroll
            for (int nt = 0; nt < 4; nt++) {
                size_t r0 = mrow + mt * 16 + g;
                int cc = ncol + nt * 8 + t2;
                *(__half2*)(T + r0 * OUT_ + cc) =
                    __floats2half2_rn(c[mt][nt][0], c[mt][nt][1]);
                *(__half2*)(T + (r0 + 8) * OUT_ + cc) =
                    __floats2half2_rn(c[mt][nt][2], c[mt][nt][3]);
            }
    } else {
        float* O = (float*)Dout;
#pragma unroll
        for (int mt = 0; mt < 4; mt++)
#pragma unroll
            for (int nt = 0; nt < 4; nt++) {
                int cc = ncol + nt * 8 + t2;
#pragma unroll
                for (int h = 0; h < 2; h++) {
                    size_t m = mrow + mt * 16 + g + h * 8;
                    int o = (int)(m - (size_t)b_idx * OUT_);
                    float v0 = c[mt][nt][h * 2], v1 = c[mt][nt][h * 2 + 1];
                    if (cc == o)     v0 += s1s3[m];
                    if (cc + 1 == o) v1 += s1s3[m];
                    float2* p = (float2*)(O + m * OUT_ + cc);
                    *p = make_float2(v0, v1);
                }
            }
    }
}

// ---------------- launch ----------------
extern "C" void kernel_launch(void* const* d_in, const int* in_sizes, int n_in,
                              void* d_out, int out_size) {
    const float* mu    = (const float*)d_in[0];
    const float* sigma = (const float*)d_in[1];
    const float* W     = (const float*)d_in[2];
    const float* bias  = (const float*)d_in[3];
    const float* sw    = (const float*)d_in[4];
    const float* sbias = (const float*)d_in[5];
    float* out = (float*)d_out;

    float *sp, *dp, *s1s3;
    __half *T16, *Wf, *WfT;
    cudaGetSymbolAddress((void**)&sp,   g_sp);
    cudaGetSymbolAddress((void**)&dp,   g_dp);
    cudaGetSymbolAddress((void**)&s1s3, g_s1s3);
    cudaGetSymbolAddress((void**)&T16,  g_T16);
    cudaGetSymbolAddress((void**)&Wf,   g_Wf);
    cudaGetSymbolAddress((void**)&WfT,  g_WfT);

    prep_kernel<<<(OUT_ * IN_ + 255) / 256, 256>>>(sw, mu, sigma, W, sp, dp, Wf, WfT);

    // mu_f and s1s3 (fp32, exact)
    gemm_f32<1><<<dim3(OUT_ / BNF, B_ / BMF), 256>>>(mu, W, out, bias, B_, OUT_, IN_);
    gemm_f32<2><<<dim3(OUT_ / BNF, B_ / BMF), 256>>>(dp, sp, s1s3, sbias, B_, OUT_, IN_);

    // stage 1: T[(b,i), p] = sum_j sigma[b,i,j] * W[p,j]   (M = 196608)
    hgemm<1><<<dim3(OUT_ / BN, (B_ * IN_) / BM), 256>>>(
        sigma, nullptr, WfT, T16, nullptr);

    // stage 2: out[(b,o), p] = sum_i W[o,i] * T[b,i,p] + diag  (M = 147456)
    hgemm<2><<<dim3(OUT_ / BN, (B_ * OUT_) / BM), 256>>>(
        nullptr, Wf, T16, out + (size_t)B_ * OUT_, s1s3);
}

// round 7
// speedup vs baseline: 1.0012x; 1.0001x over previous
#include <cuda_runtime.h>
#include <cuda_fp16.h>
#include <cstdint>

#define B_   384
#define IN_  512
#define OUT_ 384

// ---------------- device-global scratch ----------------
__device__ __half g_T16[(size_t)B_ * IN_ * OUT_];  // T[b][i][p]  (rows (b,i), cols p)
__device__ __half g_Wf[OUT_ * IN_];                // fp16(W)   [o][i]
__device__ __half g_WfT[IN_ * OUT_];               // fp16(W)^T [i][o]
__device__ float  g_sp[OUT_ * IN_];
__device__ float  g_dp[B_ * IN_];
__device__ float  g_s1s3[B_ * OUT_];

// ---------------- prep ----------------
__global__ void prep_kernel(const float* __restrict__ sw,
                            const float* __restrict__ mu,
                            const float* __restrict__ sigma,
                            const float* __restrict__ W,
                            float* __restrict__ sp, float* __restrict__ dp,
                            __half* __restrict__ Wf, __half* __restrict__ WfT) {
    int idx = blockIdx.x * blockDim.x + threadIdx.x;
    if (idx >= OUT_ * IN_) return;
    sp[idx] = log1pf(expf(sw[idx]));
    float w = W[idx];
    __half wh = __float2half(w);
    Wf[idx] = wh;
    int o = idx >> 9, i = idx & 511;
    WfT[i * OUT_ + o] = wh;
    int b = o;  // B_*IN_ == OUT_*IN_
    float m = mu[idx];
    dp[idx] = sigma[(size_t)b * (IN_ * IN_) + (size_t)i * (IN_ + 1)] + m * m;
}

// ---------------- small fp32 GEMM (mu_f, s1s3) ----------------
#define BMF 128
#define BNF 128
#define BKF 16
__device__ __forceinline__ unsigned long long pack2(float lo, float hi) {
    unsigned long long d; asm("mov.b64 %0, {%1, %2};" : "=l"(d) : "f"(lo), "f"(hi)); return d;
}
__device__ __forceinline__ unsigned long long dup2(float v) {
    unsigned long long d; asm("mov.b64 %0, {%1, %1};" : "=l"(d) : "f"(v)); return d;
}
__device__ __forceinline__ void unpack2(unsigned long long d, float& lo, float& hi) {
    asm("mov.b64 {%0, %1}, %2;" : "=f"(lo), "=f"(hi) : "l"(d));
}
__device__ __forceinline__ void fma2(unsigned long long& a, unsigned long long x,
                                     unsigned long long y) {
    asm("fma.rn.f32x2 %0, %1, %2, %0;" : "+l"(a) : "l"(x), "l"(y));
}
template <int EPI>
__global__ __launch_bounds__(256)
void gemm_f32(const float* __restrict__ A, const float* __restrict__ Bm,
              float* __restrict__ C, const float* __restrict__ aux,
              int M, int N, int K) {
    __shared__ float As[BKF][BMF + 4];
    __shared__ float Bs[BKF][BNF + 4];
    const int bm = blockIdx.y * BMF, bn = blockIdx.x * BNF;
    const int tid = threadIdx.x, tx = tid & 15, ty = tid >> 4;
    unsigned long long acc[8][4];
#pragma unroll
    for (int i = 0; i < 8; i++)
#pragma unroll
        for (int j = 0; j < 4; j++) acc[i][j] = 0ull;
    const int lr = tid >> 2, lq = tid & 3;
    for (int k0 = 0; k0 < K; k0 += BKF) {
#pragma unroll
        for (int l = 0; l < 2; l++) {
            int row = lr + l * 64;
            float4 v = *(const float4*)(A + (long)(bm + row) * K + k0 + lq * 4);
            As[lq * 4 + 0][row] = v.x; As[lq * 4 + 1][row] = v.y;
            As[lq * 4 + 2][row] = v.z; As[lq * 4 + 3][row] = v.w;
            float4 w = *(const float4*)(Bm + (long)(bn + row) * K + k0 + lq * 4);
            Bs[lq * 4 + 0][row] = w.x; Bs[lq * 4 + 1][row] = w.y;
            Bs[lq * 4 + 2][row] = w.z; Bs[lq * 4 + 3][row] = w.w;
        }
        __syncthreads();
#pragma unroll
        for (int k = 0; k < BKF; k++) {
            float4 a0 = *(const float4*)&As[k][ty * 8];
            float4 a1 = *(const float4*)&As[k][ty * 8 + 4];
            float4 b0 = *(const float4*)&Bs[k][tx * 8];
            float4 b1 = *(const float4*)&Bs[k][tx * 8 + 4];
            unsigned long long bb[4] = {pack2(b0.x, b0.y), pack2(b0.z, b0.w),
                                        pack2(b1.x, b1.y), pack2(b1.z, b1.w)};
            float av[8] = {a0.x, a0.y, a0.z, a0.w, a1.x, a1.y, a1.z, a1.w};
#pragma unroll
            for (int i = 0; i < 8; i++) {
                unsigned long long ad = dup2(av[i]);
#pragma unroll
                for (int j = 0; j < 4; j++) fma2(acc[i][j], ad, bb[j]);
            }
        }
        __syncthreads();
    }
#pragma unroll
    for (int i = 0; i < 8; i++) {
        int gm = bm + ty * 8 + i;
        float o[8];
#pragma unroll
        for (int j = 0; j < 4; j++) unpack2(acc[i][j], o[2 * j], o[2 * j + 1]);
#pragma unroll
        for (int j = 0; j < 8; j++) {
            int gn = bn + tx * 8 + j;
            if (EPI == 1) o[j] += aux[gn];
            if (EPI == 2) { if (gm == gn) o[j] += aux[gn]; }
        }
        float* cp = C + (long)gm * N + bn + tx * 8;
        *(float4*)(cp) = make_float4(o[0], o[1], o[2], o[3]);
        *(float4*)(cp + 4) = make_float4(o[4], o[5], o[6], o[7]);
    }
}

// ---------------- HMMA helpers ----------------
__device__ __forceinline__ uint32_t smem_u32(const void* p) {
    uint32_t a;
    asm("{ .reg .u64 t; cvta.to.shared.u64 t, %1; cvt.u32.u64 %0, t; }" : "=r"(a) : "l"(p));
    return a;
}
__device__ __forceinline__ void ldsm_x4(uint32_t* r, uint32_t addr) {
    asm volatile("ldmatrix.sync.aligned.m8n8.x4.shared.b16 {%0,%1,%2,%3}, [%4];"
                 : "=r"(r[0]), "=r"(r[1]), "=r"(r[2]), "=r"(r[3]) : "r"(addr));
}
__device__ __forceinline__ void ldsm_x4_t(uint32_t* r, uint32_t addr) {
    asm volatile("ldmatrix.sync.aligned.m8n8.x4.trans.shared.b16 {%0,%1,%2,%3}, [%4];"
                 : "=r"(r[0]), "=r"(r[1]), "=r"(r[2]), "=r"(r[3]) : "r"(addr));
}
__device__ __forceinline__ void mma16816(float* c, const uint32_t* a, const uint32_t* b) {
    asm volatile(
        "mma.sync.aligned.m16n8k16.row.col.f32.f16.f16.f32 "
        "{%0,%1,%2,%3}, {%4,%5,%6,%7}, {%8,%9}, {%0,%1,%2,%3};"
        : "+f"(c[0]), "+f"(c[1]), "+f"(c[2]), "+f"(c[3])
        : "r"(a[0]), "r"(a[1]), "r"(a[2]), "r"(a[3]), "r"(b[0]), "r"(b[1]));
}

// ---------------- main HMMA GEMM ----------------
// D[m, n] = sum_k A[m,k] * Bk[k,n]
// STAGE 1: A = sigma (fp32->fp16), Bk = WfT, D -> T (fp16, row-major)
// STAGE 2: A = Wf rows (o-block),  Bk = T[b],  D -> out rows (b,o) + diag
#define BM 128
#define BN 128
#define BK 32
#define LDA 40   // As row stride (halves)
#define LDB 136  // Bs row stride (halves)

template <int STAGE>
__global__ __launch_bounds__(256)
void hgemm(const float* __restrict__ A32, const __half* __restrict__ A16,
           const __half* __restrict__ Bsrc0, void* __restrict__ Dout,
           const float* __restrict__ s1s3) {
    __shared__ __half As[2][BM][LDA];
    __shared__ __half Bs[2][BK][LDB];

    const int tid = threadIdx.x, lane = tid & 31, wid = tid >> 5;
    const int wm = wid & 1, wn = wid >> 1;
    const int mb = blockIdx.y, nb = blockIdx.x;
    const size_t m0 = (size_t)mb * BM;
    const int n0 = nb * BN;

    // per-stage source pointers
    const int b_idx = (STAGE == 2) ? (mb / 3) : 0;
    const int o0    = (STAGE == 2) ? ((mb % 3) * BM) : 0;
    const __half* Bsrc = (STAGE == 2)
        ? Bsrc0 + (size_t)b_idx * IN_ * OUT_   // T[b]: [i][p]
        : Bsrc0;                               // WfT:  [i][o]

    // fill mappings
    const int ar = tid >> 1, akc = (tid & 1) * 16;        // A: row, 16-col chunk
    const int bkr = tid >> 3, bnc = (tid & 7) * 16;       // B: k-row, 16-col chunk

    float c[4][4][4];
#pragma unroll
    for (int i = 0; i < 4; i++)
#pragma unroll
        for (int j = 0; j < 4; j++)
#pragma unroll
            for (int l = 0; l < 4; l++) c[i][j][l] = 0.f;

    // staging registers
    float  fa[16];
    uint4  ha[2];
    uint4  hb[2];

    auto load_regs = [&](int kt) {
        const int k0 = kt * BK;
        if (STAGE == 1) {
            const float* s = A32 + (m0 + ar) * IN_ + k0 + akc;
#pragma unroll
            for (int q = 0; q < 4; q++) {
                float4 v = *(const float4*)(s + q * 4);
                fa[q * 4 + 0] = v.x; fa[q * 4 + 1] = v.y;
                fa[q * 4 + 2] = v.z; fa[q * 4 + 3] = v.w;
            }
        } else {
            const __half* s = A16 + (size_t)(o0 + ar) * IN_ + k0 + akc;
            ha[0] = *(const uint4*)(s);
            ha[1] = *(const uint4*)(s + 8);
        }
        const __half* bs = Bsrc + (size_t)(k0 + bkr) * OUT_ + n0 + bnc;
        hb[0] = *(const uint4*)(bs);
        hb[1] = *(const uint4*)(bs + 8);
    };
    auto sts = [&](int buf) {
        if (STAGE == 1) {
            __half h[16];
#pragma unroll
            for (int q = 0; q < 16; q++) h[q] = __float2half(fa[q]);
            *(uint4*)&As[buf][ar][akc]     = *(uint4*)&h[0];
            *(uint4*)&As[buf][ar][akc + 8] = *(uint4*)&h[8];
        } else {
            *(uint4*)&As[buf][ar][akc]     = ha[0];
            *(uint4*)&As[buf][ar][akc + 8] = ha[1];
        }
        *(uint4*)&Bs[buf][bkr][bnc]     = hb[0];
        *(uint4*)&Bs[buf][bkr][bnc + 8] = hb[1];
    };

    const uint32_t as_base = smem_u32(&As[0][0][0]);
    const uint32_t bs_base = smem_u32(&Bs[0][0][0]);
    const int lrow = lane & 15, lcol = (lane >> 4) * 8;

    load_regs(0);
    sts(0);
    __syncthreads();

    const int NKT = IN_ / BK;  // 16
    for (int kt = 0; kt < NKT; kt++) {
        const int cur = kt & 1;
        if (kt + 1 < NKT) load_regs(kt + 1);

#pragma unroll
        for (int ks = 0; ks < 2; ks++) {
            uint32_t af[4][4], bf[4][2];
#pragma unroll
            for (int mt = 0; mt < 4; mt++) {
                uint32_t addr = as_base +
                    ((cur * BM + wm * 64 + mt * 16 + lrow) * LDA + ks * 16 + lcol) * 2;
                ldsm_x4(af[mt], addr);
            }
#pragma unroll
            for (int np = 0; np < 2; np++) {
                uint32_t r[4];
                uint32_t addr = bs_base +
                    ((cur * BK + ks * 16 + lrow) * LDB + wn * 32 + np * 16 + lcol) * 2;
                ldsm_x4_t(r, addr);
                bf[np * 2][0] = r[0]; bf[np * 2][1] = r[1];
                bf[np * 2 + 1][0] = r[2]; bf[np * 2 + 1][1] = r[3];
            }
#pragma unroll
            for (int mt = 0; mt < 4; mt++)
#pragma unroll
                for (int nt = 0; nt < 4; nt++) mma16816(c[mt][nt], af[mt], bf[nt]);
        }
        __syncthreads();
        if (kt + 1 < NKT) {
            sts(cur ^ 1);
            __syncthreads();
        }
    }

    // ---- epilogue
    const int g = lane >> 2, t2 = (lane & 3) * 2;
    const size_t mrow = m0 + wm * 64;
    const int ncol = n0 + wn * 32;

    if (STAGE == 1) {
        __half* T = (__half*)Dout;
#pragma unroll
        for (int mt = 0; mt < 4; mt++)
#pragma unroll
            for (int nt = 0; nt < 4; nt++) {
                size_t r0 = mrow + mt * 16 + g;
                int cc = ncol + nt * 8 + t2;
                *(__half2*)(T + r0 * OUT_ + cc) =
                    __floats2half2_rn(c[mt][nt][0], c[mt][nt][1]);
                *(__half2*)(T + (r0 + 8) * OUT_ + cc) =
                    __floats2half2_rn(c[mt][nt][2], c[mt][nt][3]);
            }
    } else {
        float* O = (float*)Dout;
#pragma unroll
        for (int mt = 0; mt < 4; mt++)
#pragma unroll
            for (int nt = 0; nt < 4; nt++) {
                int cc = ncol + nt * 8 + t2;
#pragma unroll
                for (int h = 0; h < 2; h++) {
                    size_t m = mrow + mt * 16 + g + h * 8;
                    int o = (int)(m - (size_t)b_idx * OUT_);
                    float v0 = c[mt][nt][h * 2], v1 = c[mt][nt][h * 2 + 1];
                    if (cc == o)     v0 += s1s3[m];
                    if (cc + 1 == o) v1 += s1s3[m];
                    float2* p = (float2*)(O + m * OUT_ + cc);
                    *p = make_float2(v0, v1);
                }
            }
    }
}

// ---------------- launch ----------------
extern "C" void kernel_launch(void* const* d_in, const int* in_sizes, int n_in,
                              void* d_out, int out_size) {
    const float* mu    = (const float*)d_in[0];
    const float* sigma = (const float*)d_in[1];
    const float* W     = (const float*)d_in[2];
    const float* bias  = (const float*)d_in[3];
    const float* sw    = (const float*)d_in[4];
    const float* sbias = (const float*)d_in[5];
    float* out = (float*)d_out;

    float *sp, *dp, *s1s3;
    __half *T16, *Wf, *WfT;
    cudaGetSymbolAddress((void**)&sp,   g_sp);
    cudaGetSymbolAddress((void**)&dp,   g_dp);
    cudaGetSymbolAddress((void**)&s1s3, g_s1s3);
    cudaGetSymbolAddress((void**)&T16,  g_T16);
    cudaGetSymbolAddress((void**)&Wf,   g_Wf);
    cudaGetSymbolAddress((void**)&WfT,  g_WfT);

    prep_kernel<<<(OUT_ * IN_ + 255) / 256, 256>>>(sw, mu, sigma, W, sp, dp, Wf, WfT);

    // mu_f and s1s3 (fp32, exact)
    gemm_f32<1><<<dim3(OUT_ / BNF, B_ / BMF), 256>>>(mu, W, out, bias, B_, OUT_, IN_);
    gemm_f32<2><<<dim3(OUT_ / BNF, B_ / BMF), 256>>>(dp, sp, s1s3, sbias, B_, OUT_, IN_);

    // stage 1: T[(b,i), p] = sum_j sigma[b,i,j] * W[p,j]   (M = 196608)
    hgemm<1><<<dim3(OUT_ / BN, (B_ * IN_) / BM), 256>>>(
        sigma, nullptr, WfT, T16, nullptr);

    // stage 2: out[(b,o), p] = sum_i W[o,i] * T[b,i,p] + diag  (M = 147456)
    hgemm<2><<<dim3(OUT_ / BN, (B_ * OUT_) / BM), 256>>>(
        nullptr, Wf, T16, out + (size_t)B_ * OUT_, s1s3);
}

// round 8
// speedup vs baseline: 1.0012x; 1.0000x over previous
#include <cuda_runtime.h>
#include <cuda_fp16.h>
#include <cstdint>

#define B_   384
#define IN_  512
#define OUT_ 384

// ---------------- device-global scratch ----------------
__device__ __half g_T16[(size_t)B_ * IN_ * OUT_];  // T[b][i][p]  (rows (b,i), cols p)
__device__ __half g_Wf[OUT_ * IN_];                // fp16(W)   [o][i]
__device__ __half g_WfT[IN_ * OUT_];               // fp16(W)^T [i][o]
__device__ float  g_sp[OUT_ * IN_];
__device__ float  g_dp[B_ * IN_];
__device__ float  g_s1s3[B_ * OUT_];

// ---------------- prep ----------------
__global__ void prep_kernel(const float* __restrict__ sw,
                            const float* __restrict__ mu,
                            const float* __restrict__ sigma,
                            const float* __restrict__ W,
                            float* __restrict__ sp, float* __restrict__ dp,
                            __half* __restrict__ Wf, __half* __restrict__ WfT) {
    int idx = blockIdx.x * blockDim.x + threadIdx.x;
    if (idx >= OUT_ * IN_) return;
    sp[idx] = log1pf(expf(sw[idx]));
    float w = W[idx];
    __half wh = __float2half(w);
    Wf[idx] = wh;
    int o = idx >> 9, i = idx & 511;
    WfT[i * OUT_ + o] = wh;
    int b = o;  // B_*IN_ == OUT_*IN_
    float m = mu[idx];
    dp[idx] = sigma[(size_t)b * (IN_ * IN_) + (size_t)i * (IN_ + 1)] + m * m;
}

// ---------------- small fp32 GEMM (mu_f, s1s3) ----------------
#define BMF 128
#define BNF 128
#define BKF 16
__device__ __forceinline__ unsigned long long pack2(float lo, float hi) {
    unsigned long long d; asm("mov.b64 %0, {%1, %2};" : "=l"(d) : "f"(lo), "f"(hi)); return d;
}
__device__ __forceinline__ unsigned long long dup2(float v) {
    unsigned long long d; asm("mov.b64 %0, {%1, %1};" : "=l"(d) : "f"(v)); return d;
}
__device__ __forceinline__ void unpack2(unsigned long long d, float& lo, float& hi) {
    asm("mov.b64 {%0, %1}, %2;" : "=f"(lo), "=f"(hi) : "l"(d));
}
__device__ __forceinline__ void fma2(unsigned long long& a, unsigned long long x,
                                     unsigned long long y) {
    asm("fma.rn.f32x2 %0, %1, %2, %0;" : "+l"(a) : "l"(x), "l"(y));
}
template <int EPI>
__global__ __launch_bounds__(256)
void gemm_f32(const float* __restrict__ A, const float* __restrict__ Bm,
              float* __restrict__ C, const float* __restrict__ aux,
              int M, int N, int K) {
    __shared__ float As[BKF][BMF + 4];
    __shared__ float Bs[BKF][BNF + 4];
    const int bm = blockIdx.y * BMF, bn = blockIdx.x * BNF;
    const int tid = threadIdx.x, tx = tid & 15, ty = tid >> 4;
    unsigned long long acc[8][4];
#pragma unroll
    for (int i = 0; i < 8; i++)
#pragma unroll
        for (int j = 0; j < 4; j++) acc[i][j] = 0ull;
    const int lr = tid >> 2, lq = tid & 3;
    for (int k0 = 0; k0 < K; k0 += BKF) {
#pragma unroll
        for (int l = 0; l < 2; l++) {
            int row = lr + l * 64;
            float4 v = *(const float4*)(A + (long)(bm + row) * K + k0 + lq * 4);
            As[lq * 4 + 0][row] = v.x; As[lq * 4 + 1][row] = v.y;
            As[lq * 4 + 2][row] = v.z; As[lq * 4 + 3][row] = v.w;
            float4 w = *(const float4*)(Bm + (long)(bn + row) * K + k0 + lq * 4);
            Bs[lq * 4 + 0][row] = w.x; Bs[lq * 4 + 1][row] = w.y;
            Bs[lq * 4 + 2][row] = w.z; Bs[lq * 4 + 3][row] = w.w;
        }
        __syncthreads();
#pragma unroll
        for (int k = 0; k < BKF; k++) {
            float4 a0 = *(const float4*)&As[k][ty * 8];
            float4 a1 = *(const float4*)&As[k][ty * 8 + 4];
            float4 b0 = *(const float4*)&Bs[k][tx * 8];
            float4 b1 = *(const float4*)&Bs[k][tx * 8 + 4];
            unsigned long long bb[4] = {pack2(b0.x, b0.y), pack2(b0.z, b0.w),
                                        pack2(b1.x, b1.y), pack2(b1.z, b1.w)};
            float av[8] = {a0.x, a0.y, a0.z, a0.w, a1.x, a1.y, a1.z, a1.w};
#pragma unroll
            for (int i = 0; i < 8; i++) {
                unsigned long long ad = dup2(av[i]);
#pragma unroll
                for (int j = 0; j < 4; j++) fma2(acc[i][j], ad, bb[j]);
            }
        }
        __syncthreads();
    }
#pragma unroll
    for (int i = 0; i < 8; i++) {
        int gm = bm + ty * 8 + i;
        float o[8];
#pragma unroll
        for (int j = 0; j < 4; j++) unpack2(acc[i][j], o[2 * j], o[2 * j + 1]);
#pragma unroll
        for (int j = 0; j < 8; j++) {
            int gn = bn + tx * 8 + j;
            if (EPI == 1) o[j] += aux[gn];
            if (EPI == 2) { if (gm == gn) o[j] += aux[gn]; }
        }
        float* cp = C + (long)gm * N + bn + tx * 8;
        *(float4*)(cp) = make_float4(o[0], o[1], o[2], o[3]);
        *(float4*)(cp + 4) = make_float4(o[4], o[5], o[6], o[7]);
    }
}

// ---------------- HMMA helpers ----------------
__device__ __forceinline__ uint32_t smem_u32(const void* p) {
    uint32_t a;
    asm("{ .reg .u64 t; cvta.to.shared.u64 t, %1; cvt.u32.u64 %0, t; }" : "=r"(a) : "l"(p));
    return a;
}
__device__ __forceinline__ void ldsm_x4(uint32_t* r, uint32_t addr) {
    asm volatile("ldmatrix.sync.aligned.m8n8.x4.shared.b16 {%0,%1,%2,%3}, [%4];"
                 : "=r"(r[0]), "=r"(r[1]), "=r"(r[2]), "=r"(r[3]) : "r"(addr));
}
__device__ __forceinline__ void ldsm_x4_t(uint32_t* r, uint32_t addr) {
    asm volatile("ldmatrix.sync.aligned.m8n8.x4.trans.shared.b16 {%0,%1,%2,%3}, [%4];"
                 : "=r"(r[0]), "=r"(r[1]), "=r"(r[2]), "=r"(r[3]) : "r"(addr));
}
__device__ __forceinline__ void mma16816(float* c, const uint32_t* a, const uint32_t* b) {
    asm volatile(
        "mma.sync.aligned.m16n8k16.row.col.f32.f16.f16.f32 "
        "{%0,%1,%2,%3}, {%4,%5,%6,%7}, {%8,%9}, {%0,%1,%2,%3};"
        : "+f"(c[0]), "+f"(c[1]), "+f"(c[2]), "+f"(c[3])
        : "r"(a[0]), "r"(a[1]), "r"(a[2]), "r"(a[3]), "r"(b[0]), "r"(b[1]));
}

// ---------------- main HMMA GEMM ----------------
// D[m, n] = sum_k A[m,k] * Bk[k,n]
// STAGE 1: A = sigma (fp32->fp16), Bk = WfT, D -> T (fp16, row-major)
// STAGE 2: A = Wf rows (o-block),  Bk = T[b],  D -> out rows (b,o) + diag
#define BM 128
#define BN 128
#define BK 32
#define LDA 40   // As row stride (halves)
#define LDB 136  // Bs row stride (halves)

template <int STAGE>
__global__ __launch_bounds__(256)
void hgemm(const float* __restrict__ A32, const __half* __restrict__ A16,
           const __half* __restrict__ Bsrc0, void* __restrict__ Dout,
           const float* __restrict__ s1s3) {
    __shared__ __half As[2][BM][LDA];
    __shared__ __half Bs[2][BK][LDB];

    const int tid = threadIdx.x, lane = tid & 31, wid = tid >> 5;
    const int wm = wid & 1, wn = wid >> 1;
    const int mb = blockIdx.y, nb = blockIdx.x;
    const size_t m0 = (size_t)mb * BM;
    const int n0 = nb * BN;

    // per-stage source pointers
    const int b_idx = (STAGE == 2) ? (mb / 3) : 0;
    const int o0    = (STAGE == 2) ? ((mb % 3) * BM) : 0;
    const __half* Bsrc = (STAGE == 2)
        ? Bsrc0 + (size_t)b_idx * IN_ * OUT_   // T[b]: [i][p]
        : Bsrc0;                               // WfT:  [i][o]

    // fill mappings
    const int ar = tid >> 1, akc = (tid & 1) * 16;        // A: row, 16-col chunk
    const int bkr = tid >> 3, bnc = (tid & 7) * 16;       // B: k-row, 16-col chunk

    float c[4][4][4];
#pragma unroll
    for (int i = 0; i < 4; i++)
#pragma unroll
        for (int j = 0; j < 4; j++)
#pragma unroll
            for (int l = 0; l < 4; l++) c[i][j][l] = 0.f;

    // staging registers
    float  fa[16];
    uint4  ha[2];
    uint4  hb[2];

    auto load_regs = [&](int kt) {
        const int k0 = kt * BK;
        if (STAGE == 1) {
            const float* s = A32 + (m0 + ar) * IN_ + k0 + akc;
#pragma unroll
            for (int q = 0; q < 4; q++) {
                float4 v = *(const float4*)(s + q * 4);
                fa[q * 4 + 0] = v.x; fa[q * 4 + 1] = v.y;
                fa[q * 4 + 2] = v.z; fa[q * 4 + 3] = v.w;
            }
        } else {
            const __half* s = A16 + (size_t)(o0 + ar) * IN_ + k0 + akc;
            ha[0] = *(const uint4*)(s);
            ha[1] = *(const uint4*)(s + 8);
        }
        const __half* bs = Bsrc + (size_t)(k0 + bkr) * OUT_ + n0 + bnc;
        hb[0] = *(const uint4*)(bs);
        hb[1] = *(const uint4*)(bs + 8);
    };
    auto sts = [&](int buf) {
        if (STAGE == 1) {
            __half h[16];
#pragma unroll
            for (int q = 0; q < 16; q++) h[q] = __float2half(fa[q]);
            *(uint4*)&As[buf][ar][akc]     = *(uint4*)&h[0];
            *(uint4*)&As[buf][ar][akc + 8] = *(uint4*)&h[8];
        } else {
            *(uint4*)&As[buf][ar][akc]     = ha[0];
            *(uint4*)&As[buf][ar][akc + 8] = ha[1];
        }
        *(uint4*)&Bs[buf][bkr][bnc]     = hb[0];
        *(uint4*)&Bs[buf][bkr][bnc + 8] = hb[1];
    };

    const uint32_t as_base = smem_u32(&As[0][0][0]);
    const uint32_t bs_base = smem_u32(&Bs[0][0][0]);
    const int lrow = lane & 15, lcol = (lane >> 4) * 8;

    load_regs(0);
    sts(0);
    __syncthreads();

    const int NKT = IN_ / BK;  // 16
    for (int kt = 0; kt < NKT; kt++) {
        const int cur = kt & 1;
        if (kt + 1 < NKT) load_regs(kt + 1);

#pragma unroll
        for (int ks = 0; ks < 2; ks++) {
            uint32_t af[4][4], bf[4][2];
#pragma unroll
            for (int mt = 0; mt < 4; mt++) {
                uint32_t addr = as_base +
                    ((cur * BM + wm * 64 + mt * 16 + lrow) * LDA + ks * 16 + lcol) * 2;
                ldsm_x4(af[mt], addr);
            }
#pragma unroll
            for (int np = 0; np < 2; np++) {
                uint32_t r[4];
                uint32_t addr = bs_base +
                    ((cur * BK + ks * 16 + lrow) * LDB + wn * 32 + np * 16 + lcol) * 2;
                ldsm_x4_t(r, addr);
                bf[np * 2][0] = r[0]; bf[np * 2][1] = r[1];
                bf[np * 2 + 1][0] = r[2]; bf[np * 2 + 1][1] = r[3];
            }
#pragma unroll
            for (int mt = 0; mt < 4; mt++)
#pragma unroll
                for (int nt = 0; nt < 4; nt++) mma16816(c[mt][nt], af[mt], bf[nt]);
        }
        __syncthreads();
        if (kt + 1 < NKT) {
            sts(cur ^ 1);
            __syncthreads();
        }
    }

    // ---- epilogue
    const int g = lane >> 2, t2 = (lane & 3) * 2;
    const size_t mrow = m0 + wm * 64;
    const int ncol = n0 + wn * 32;

    if (STAGE == 1) {
        __half* T = (__half*)Dout;
#pragma unroll
        for (int mt = 0; mt < 4; mt++)
#pragma unroll
            for (int nt = 0; nt < 4; nt++) {
                size_t r0 = mrow + mt * 16 + g;
                int cc = ncol + nt * 8 + t2;
                *(__half2*)(T + r0 * OUT_ + cc) =
                    __floats2half2_rn(c[mt][nt][0], c[mt][nt][1]);
                *(__half2*)(T + (r0 + 8) * OUT_ + cc) =
                    __floats2half2_rn(c[mt][nt][2], c[mt][nt][3]);
            }
    } else {
        float* O = (float*)Dout;
#pragma unroll
        for (int mt = 0; mt < 4; mt++)
#pragma unroll
            for (int nt = 0; nt < 4; nt++) {
                int cc = ncol + nt * 8 + t2;
#pragma unroll
                for (int h = 0; h < 2; h++) {
                    size_t m = mrow + mt * 16 + g + h * 8;
                    int o = (int)(m - (size_t)b_idx * OUT_);
                    float v0 = c[mt][nt][h * 2], v1 = c[mt][nt][h * 2 + 1];
                    if (cc == o)     v0 += s1s3[m];
                    if (cc + 1 == o) v1 += s1s3[m];
                    float2* p = (float2*)(O + m * OUT_ + cc);
                    *p = make_float2(v0, v1);
                }
            }
    }
}

// ---------------- launch ----------------
extern "C" void kernel_launch(void* const* d_in, const int* in_sizes, int n_in,
                              void* d_out, int out_size) {
    const float* mu    = (const float*)d_in[0];
    const float* sigma = (const float*)d_in[1];
    const float* W     = (const float*)d_in[2];
    const float* bias  = (const float*)d_in[3];
    const float* sw    = (const float*)d_in[4];
    const float* sbias = (const float*)d_in[5];
    float* out = (float*)d_out;

    float *sp, *dp, *s1s3;
    __half *T16, *Wf, *WfT;
    cudaGetSymbolAddress((void**)&sp,   g_sp);
    cudaGetSymbolAddress((void**)&dp,   g_dp);
    cudaGetSymbolAddress((void**)&s1s3, g_s1s3);
    cudaGetSymbolAddress((void**)&T16,  g_T16);
    cudaGetSymbolAddress((void**)&Wf,   g_Wf);
    cudaGetSymbolAddress((void**)&WfT,  g_WfT);

    prep_kernel<<<(OUT_ * IN_ + 255) / 256, 256>>>(sw, mu, sigma, W, sp, dp, Wf, WfT);

    // mu_f and s1s3 (fp32, exact)
    gemm_f32<1><<<dim3(OUT_ / BNF, B_ / BMF), 256>>>(mu, W, out, bias, B_, OUT_, IN_);
    gemm_f32<2><<<dim3(OUT_ / BNF, B_ / BMF), 256>>>(dp, sp, s1s3, sbias, B_, OUT_, IN_);

    // stage 1: T[(b,i), p] = sum_j sigma[b,i,j] * W[p,j]   (M = 196608)
    hgemm<1><<<dim3(OUT_ / BN, (B_ * IN_) / BM), 256>>>(
        sigma, nullptr, WfT, T16, nullptr);

    // stage 2: out[(b,o), p] = sum_i W[o,i] * T[b,i,p] + diag  (M = 147456)
    hgemm<2><<<dim3(OUT_ / BN, (B_ * OUT_) / BM), 256>>>(
        nullptr, Wf, T16, out + (size_t)B_ * OUT_, s1s3);
}